// round 4
// baseline (speedup 1.0000x reference)
#include <cuda_runtime.h>

// ---------------------------------------------------------------------------
// MomGRU persistent recurrence, round 4.
// R2 skeleton (L2 h-exchange + aligned cluster barrier) with 512 threads:
// 16 batch-blocks x 8 hidden-blocks = 128 CTAs, cluster(8) per batch block.
// Thread = (u 0..31, bq 0..1, ks 0..7): K split 8-way, 3-level bfly reduce.
// x prefetch hoisted above the barrier wait; beta after GEMM (overlaps the
// other warps' reduction). h global layout [buf][batch][hid].
// ---------------------------------------------------------------------------

namespace {
constexpr int BATCH = 128;
constexpr int SEQ   = 1024;
constexpr int HID   = 256;
constexpr int GB    = 16;              // batch blocks
constexpr int GH    = 8;               // hidden blocks (= cluster size)
constexpr int NCTA  = GB * GH;         // 128
constexpr int BB    = BATCH / GB;      // 8 batches per CTA
constexpr int UPC   = HID / GH;        // 32 hidden units per CTA
constexpr int NROWS = 3 * UPC;         // 96 W_hh rows per CTA
constexpr int NTH   = 512;
constexpr int RSW   = HID + 16;        // 272 weight row stride (floats)
constexpr int RSH   = HID + 4;         // 260 h row stride (floats)

// smem layout (floats)
constexpr int OFF_W   = 0;                       // NROWS * RSW
constexpr int OFF_H   = OFF_W + NROWS * RSW;     // BB * RSH (single staging buf)
constexpr int OFF_WBH = OFF_H + BB * RSH;        // HID
constexpr int OFF_WHD = OFF_WBH + HID;           // HID
constexpr int OFF_BS  = OFF_WHD + HID;           // BB
constexpr int OFF_XS  = OFF_BS + BB;             // BB float2
constexpr int SMEM_FLOATS = OFF_XS + BB * 2;
constexpr int SMEM_BYTES  = SMEM_FLOATS * 4;     // ~114.9 KB
}

// persistent h ping-pong, layout [buf][batch][hid]
__device__ float g_h[2][BATCH][HID];

// ---- packed fp32x2 helpers -------------------------------------------------
__device__ __forceinline__ unsigned long long pk2(float2 v) {
    unsigned long long r;
    asm("mov.b64 %0, {%1,%2};" : "=l"(r) : "f"(v.x), "f"(v.y));
    return r;
}
__device__ __forceinline__ float2 upk2(unsigned long long v) {
    float2 r;
    asm("mov.b64 {%0,%1}, %2;" : "=f"(r.x), "=f"(r.y) : "l"(v));
    return r;
}
__device__ __forceinline__ float2 ffma2(float2 a, float2 b, float2 c) {
    unsigned long long d;
    asm("fma.rn.f32x2 %0, %1, %2, %3;"
        : "=l"(d) : "l"(pk2(a)), "l"(pk2(b)), "l"(pk2(c)));
    return upk2(d);
}

__device__ __forceinline__ float sigf(float x) {
    return __fdividef(1.0f, 1.0f + __expf(-x));
}
__device__ __forceinline__ float tanh_fast(float x) {
    float ax = fabsf(x);
    float e  = __expf(-2.0f * ax);
    return copysignf(__fdividef(1.0f - e, 1.0f + e), x);
}

#define CLUSTER_ARRIVE() asm volatile("barrier.cluster.arrive.aligned;" ::: "memory")
#define CLUSTER_WAIT()   asm volatile("barrier.cluster.wait.aligned;"   ::: "memory")

extern "C" __global__ void __launch_bounds__(NTH, 1) __cluster_dims__(GH, 1, 1)
momgru_kernel(const float* __restrict__ x,
              const float* __restrict__ W_ih,
              const float* __restrict__ W_hh,
              const float* __restrict__ b_ih,
              const float* __restrict__ b_hh,
              const float* __restrict__ Wb_x,
              const float* __restrict__ Wb_h,
              const float* __restrict__ b_beta,
              const float* __restrict__ s_ptr,
              const float* __restrict__ W_head,
              const float* __restrict__ b_head,
              float* __restrict__ out)
{
    extern __shared__ float sm[];
    float*  ws     = sm + OFF_W;
    float*  hs     = sm + OFF_H;
    float*  wbhs   = sm + OFF_WBH;
    float*  whds   = sm + OFF_WHD;
    float*  beta_s = sm + OFF_BS;
    float2* xs     = (float2*)(sm + OFF_XS);

    const int tid = threadIdx.x;
    const int j   = blockIdx.x & (GH - 1);    // hidden block / cluster rank
    const int i   = blockIdx.x >> 3;          // batch block
    const int b0  = i * BB;
    const int u0  = j * UPC;

    const int u  = tid >> 4;        // 0..31  hidden unit (local)
    const int bq = (tid >> 3) & 1;  // 0..1   batch quad
    const int ks = tid & 7;         // 0..7   K-split lane

    // ---- one-time preload ----------------------------------------------------
    for (int e = tid; e < NROWS * HID; e += NTH) {
        int row = e >> 8;
        int k   = e & (HID - 1);
        int g   = row >> 5;
        int uu  = row & 31;
        ws[row * RSW + k] = W_hh[(g * HID + u0 + uu) * HID + k];
    }
    for (int e = tid; e < HID; e += NTH) {
        wbhs[e] = Wb_h[e];
        whds[e] = W_head[e];
    }
    const float wbx0  = __ldg(Wb_x);
    const float wbx1  = __ldg(Wb_x + 1);
    const float bbeta = __ldg(b_beta);
    const float sv    = __ldg(s_ptr);
    const float bhead = __ldg(b_head);

    float2 wihg[3];
    float  bihg[3], bhhg[3];
    #pragma unroll
    for (int g = 0; g < 3; ++g) {
        int gr  = g * HID + u0 + u;
        wihg[g] = make_float2(__ldg(W_ih + gr * 2), __ldg(W_ih + gr * 2 + 1));
        bihg[g] = __ldg(b_ih + gr);
        bhhg[g] = __ldg(b_hh + gr);
    }

    // zero h0: owner threads (ks<4) zero their (b,u) slots
    if (ks < 4) {
        int bg = bq * 4 + ks;
        __stcg(&g_h[0][b0 + bg][u0 + u], 0.0f);
    }
    CLUSTER_ARRIVE();   // release: h0 zeros visible to cluster at first wait

    // per-owner momentum state (valid on ks<4 threads)
    float v0 = 0.f, v1 = 0.f, v2 = 0.f;

    const float* w0p = ws + (0 * UPC + u) * RSW + ks * 4;
    const float* w1p = ws + (1 * UPC + u) * RSW + ks * 4;
    const float* w2p = ws + (2 * UPC + u) * RSW + ks * 4;
    const float* h0p = hs + (bq * 4 + 0) * RSH + ks * 4;
    const float* h1p = hs + (bq * 4 + 1) * RSH + ks * 4;
    const float* h2p = hs + (bq * 4 + 2) * RSH + ks * 4;
    const float* h3p = hs + (bq * 4 + 3) * RSH + ks * 4;

    const int bb = tid >> 3;        // beta batch (tid<64)
    const int kc = tid & 7;         // beta K-chunk lane

    for (int t = 0; t < SEQ; ++t) {
        // x prefetch BEFORE the barrier wait (independent of peers' h)
        float2 xv = make_float2(0.f, 0.f);
        if (tid < 64 && kc == 0)
            xv = __ldg((const float2*)x + (b0 + bb) * SEQ + t);

        CLUSTER_WAIT();   // acquire: peers' h_t stores visible in L2

        // ---- load h_t -> smem staging (1 LDG.128 per thread) -----------------
        {
            const float* hsrc = &g_h[t & 1][b0][0];
            float4 hv = __ldcg((const float4*)hsrc + tid);
            int b = tid >> 6;
            int q = tid & 63;
            *(float4*)(hs + b * RSH + q * 4) = hv;
        }
        __syncthreads();

        // ---- gh = h @ W_hh^T : f32x2 over K, thread does (3 g x 4 b), K/8 ----
        float2 acc[3][4];
        #pragma unroll
        for (int g = 0; g < 3; ++g)
            #pragma unroll
            for (int bi = 0; bi < 4; ++bi) acc[g][bi] = make_float2(0.f, 0.f);

        #pragma unroll
        for (int kk = 0; kk < 8; ++kk) {
            const int o = kk * 32;
            float4 w4[3], h4[4];
            w4[0] = *(const float4*)(w0p + o);
            w4[1] = *(const float4*)(w1p + o);
            w4[2] = *(const float4*)(w2p + o);
            h4[0] = *(const float4*)(h0p + o);
            h4[1] = *(const float4*)(h1p + o);
            h4[2] = *(const float4*)(h2p + o);
            h4[3] = *(const float4*)(h3p + o);
            #pragma unroll
            for (int g = 0; g < 3; ++g)
                #pragma unroll
                for (int bi = 0; bi < 4; ++bi)
                    acc[g][bi] = ffma2(make_float2(w4[g].x, w4[g].y),
                                       make_float2(h4[bi].x, h4[bi].y), acc[g][bi]);
            #pragma unroll
            for (int g = 0; g < 3; ++g)
                #pragma unroll
                for (int bi = 0; bi < 4; ++bi)
                    acc[g][bi] = ffma2(make_float2(w4[g].z, w4[g].w),
                                       make_float2(h4[bi].z, h4[bi].w), acc[g][bi]);
        }

        // ---- beta (warps 0-1, AFTER their GEMM; overlaps others' reduce) -----
        if (tid < 64) {
            const float* hrow = hs + bb * RSH + kc * 4;
            const float* wrow = wbhs + kc * 4;
            float2 a2 = make_float2(0.f, 0.f);
            #pragma unroll
            for (int kk = 0; kk < 8; ++kk) {
                float4 h4 = *(const float4*)(hrow + kk * 32);
                float4 w4 = *(const float4*)(wrow + kk * 32);
                a2 = ffma2(make_float2(w4.x, w4.y), make_float2(h4.x, h4.y), a2);
                a2 = ffma2(make_float2(w4.z, w4.w), make_float2(h4.z, h4.w), a2);
            }
            float a = a2.x + a2.y;
            a += __shfl_xor_sync(0xffffffffu, a, 1);
            a += __shfl_xor_sync(0xffffffffu, a, 2);
            a += __shfl_xor_sync(0xffffffffu, a, 4);
            if (kc == 0) {
                float bval = sigf(xv.x * wbx0 + xv.y * wbx1 + a + bbeta);
                beta_s[bb] = bval;
                xs[bb]     = xv;
                if (j == 0) out[BATCH + (b0 + bb) * SEQ + t] = bval;
            }
        }

        // ---- K-split reduce (bfly over 8 ks lanes) ----------------------------
        float gsum[3][4];
        #pragma unroll
        for (int g = 0; g < 3; ++g)
            #pragma unroll
            for (int bi = 0; bi < 4; ++bi) {
                float sc = acc[g][bi].x + acc[g][bi].y;
                sc += __shfl_xor_sync(0xffffffffu, sc, 1);
                sc += __shfl_xor_sync(0xffffffffu, sc, 2);
                sc += __shfl_xor_sync(0xffffffffu, sc, 4);
                gsum[g][bi] = sc;
            }

        __syncthreads();   // beta_s / xs published

        // ---- v update + gates on owner threads (ks<4): batch bg = bq*4+ks ----
        if (ks < 4) {
            const int    bg    = bq * 4 + ks;
            const float  be    = beta_s[bg];
            const float2 xv2   = xs[bg];
            const float  hprev = hs[bg * RSH + u0 + u];

            float pr = xv2.x * wihg[0].x + xv2.y * wihg[0].y + bihg[0];
            float pz = xv2.x * wihg[1].x + xv2.y * wihg[1].y + bihg[1];
            float pn = xv2.x * wihg[2].x + xv2.y * wihg[2].y + bihg[2];
            v0 = be * v0 + sv * pr;
            v1 = be * v1 + sv * pz;
            v2 = be * v2 + sv * pn;

            float ghr = gsum[0][ks] + bhhg[0];
            float ghz = gsum[1][ks] + bhhg[1];
            float ghn = gsum[2][ks] + bhhg[2];

            float r  = sigf(v0 + ghr);
            float z  = sigf(v1 + ghz);
            float n  = tanh_fast(v2 + r * ghn);
            float hn = (1.0f - z) * n + z * hprev;

            __stcg(&g_h[(t + 1) & 1][b0 + bg][u0 + u], hn);
        }

        CLUSTER_ARRIVE();  // release h_{t+1} stores
    }

    CLUSTER_WAIT();        // final h_T (buffer 0) visible

    // ---- head: out[b] = h_T . W_head + b_head (rank-0 CTA per batch block) ---
    if (j == 0 && tid < 64) {
        int b = tid >> 3;
        const float* hT = &g_h[0][b0 + b][0];
        float2 a2 = make_float2(0.f, 0.f);
        #pragma unroll
        for (int kk = 0; kk < 8; ++kk) {
            float4 h4 = __ldcg((const float4*)(hT + kc * 4 + kk * 32));
            float4 w4 = *(const float4*)(whds + kc * 4 + kk * 32);
            a2 = ffma2(make_float2(w4.x, w4.y), make_float2(h4.x, h4.y), a2);
            a2 = ffma2(make_float2(w4.z, w4.w), make_float2(h4.z, h4.w), a2);
        }
        float a = a2.x + a2.y;
        a += __shfl_xor_sync(0xffffffffu, a, 1);
        a += __shfl_xor_sync(0xffffffffu, a, 2);
        a += __shfl_xor_sync(0xffffffffu, a, 4);
        if (kc == 0) out[b0 + b] = a + bhead;
    }
}

extern "C" void kernel_launch(void* const* d_in, const int* in_sizes, int n_in,
                              void* d_out, int out_size) {
    const float* x      = (const float*)d_in[0];
    const float* W_ih   = (const float*)d_in[1];
    const float* W_hh   = (const float*)d_in[2];
    const float* b_ih   = (const float*)d_in[3];
    const float* b_hh   = (const float*)d_in[4];
    const float* Wb_x   = (const float*)d_in[5];
    const float* Wb_h   = (const float*)d_in[6];
    const float* b_beta = (const float*)d_in[7];
    const float* s      = (const float*)d_in[8];
    const float* W_head = (const float*)d_in[9];
    const float* b_head = (const float*)d_in[10];

    cudaFuncSetAttribute(momgru_kernel,
                         cudaFuncAttributeMaxDynamicSharedMemorySize,
                         SMEM_BYTES);

    momgru_kernel<<<NCTA, NTH, SMEM_BYTES>>>(
        x, W_ih, W_hh, b_ih, b_hh, Wb_x, Wb_h, b_beta, s, W_head, b_head,
        (float*)d_out);
}

// round 6
// speedup vs baseline: 1.1916x; 1.1916x over previous
#include <cuda_runtime.h>

// ---------------------------------------------------------------------------
// MomGRU persistent recurrence, round 6 = R2 compute skeleton + mbarrier sync.
// 128 CTAs = 16 batch-blocks x 8 hidden-blocks, cluster(8) per batch block,
// 256 threads. h exchanged via stcg/ldcg in L2 (batch-major [buf][B][H]);
// per-step sync = two ping-pong smem mbarriers (count 8), remote arrives by
// threads 0..7 after fence.acq_rel.cluster, local try_wait.parity.acquire.
// ---------------------------------------------------------------------------

namespace {
constexpr int BATCH = 128;
constexpr int SEQ   = 1024;
constexpr int HID   = 256;
constexpr int GB    = 16;              // batch blocks
constexpr int GH    = 8;               // hidden blocks (= cluster size)
constexpr int NCTA  = GB * GH;         // 128
constexpr int BB    = BATCH / GB;      // 8 batches per CTA
constexpr int UPC   = HID / GH;        // 32 hidden units per CTA
constexpr int NROWS = 3 * UPC;         // 96 W_hh rows per CTA
constexpr int NTH   = 256;
constexpr int RSW   = HID + 16;        // 272 weight row stride (floats)
constexpr int RSH   = HID + 4;         // 260 h row stride (floats)

// smem layout (floats)
constexpr int OFF_MBAR = 0;                      // 2 mbarriers = 16B
constexpr int OFF_W   = 4;                       // NROWS * RSW
constexpr int OFF_H   = OFF_W + NROWS * RSW;     // BB * RSH
constexpr int OFF_WBH = OFF_H + BB * RSH;        // HID
constexpr int OFF_WHD = OFF_WBH + HID;           // HID
constexpr int OFF_BS  = OFF_WHD + HID;           // BB
constexpr int OFF_XS  = OFF_BS + BB;             // BB float2
constexpr int SMEM_FLOATS = OFF_XS + BB * 2;
constexpr int SMEM_BYTES  = SMEM_FLOATS * 4;     // ~114.9 KB
}

// persistent h ping-pong, layout [buf][batch][hid]  (R2/R4-proven)
__device__ float g_h[2][BATCH][HID];

// ---- packed fp32x2 helpers -------------------------------------------------
__device__ __forceinline__ unsigned long long pk2(float2 v) {
    unsigned long long r;
    asm("mov.b64 %0, {%1,%2};" : "=l"(r) : "f"(v.x), "f"(v.y));
    return r;
}
__device__ __forceinline__ float2 upk2(unsigned long long v) {
    float2 r;
    asm("mov.b64 {%0,%1}, %2;" : "=f"(r.x), "=f"(r.y) : "l"(v));
    return r;
}
__device__ __forceinline__ float2 ffma2(float2 a, float2 b, float2 c) {
    unsigned long long d;
    asm("fma.rn.f32x2 %0, %1, %2, %3;"
        : "=l"(d) : "l"(pk2(a)), "l"(pk2(b)), "l"(pk2(c)));
    return upk2(d);
}

__device__ __forceinline__ float sigf(float x) {
    return __fdividef(1.0f, 1.0f + __expf(-x));
}
__device__ __forceinline__ float tanh_fast(float x) {
    float ax = fabsf(x);
    float e  = __expf(-2.0f * ax);
    return copysignf(__fdividef(1.0f - e, 1.0f + e), x);
}

// ---- mbarrier / cluster helpers ---------------------------------------------
__device__ __forceinline__ unsigned smem_u32(const void* p) {
    unsigned a;
    asm("{ .reg .u64 t; cvta.to.shared.u64 t, %1; cvt.u32.u64 %0, t; }"
        : "=r"(a) : "l"(p));
    return a;
}
__device__ __forceinline__ void mbar_init(unsigned mbar, unsigned cnt) {
    asm volatile("mbarrier.init.shared.b64 [%0], %1;" :: "r"(mbar), "r"(cnt) : "memory");
}
__device__ __forceinline__ void mbar_arrive_peer(unsigned local_mbar, unsigned rank) {
    asm volatile(
        "{\n\t.reg .b32 r;\n\t"
        "mapa.shared::cluster.u32 r, %0, %1;\n\t"
        "mbarrier.arrive.release.cluster.shared::cluster.b64 _, [r];\n\t}"
        :: "r"(local_mbar), "r"(rank) : "memory");
}
__device__ __forceinline__ void mbar_wait(unsigned mbar, unsigned parity) {
    unsigned done;
    asm volatile(
        "{\n\t.reg .pred p;\n\t"
        "mbarrier.try_wait.parity.acquire.cluster.shared::cta.b64 p, [%1], %2;\n\t"
        "selp.b32 %0, 1, 0, p;\n\t}"
        : "=r"(done) : "r"(mbar), "r"(parity) : "memory");
    if (!done) {
        asm volatile(
            "{\n\t.reg .pred P1;\n\t"
            "WL_%=:\n\t"
            "mbarrier.try_wait.parity.acquire.cluster.shared::cta.b64 P1, [%0], %1, 0x989680;\n\t"
            "@P1 bra.uni WD_%=;\n\t"
            "bra.uni WL_%=;\n\t"
            "WD_%=:\n\t}"
            :: "r"(mbar), "r"(parity) : "memory");
    }
}
#define CLUSTER_SYNC_() do {                                          \
    asm volatile("barrier.cluster.arrive.aligned;" ::: "memory");     \
    asm volatile("barrier.cluster.wait.aligned;"   ::: "memory");     \
} while (0)

extern "C" __global__ void __launch_bounds__(NTH, 1) __cluster_dims__(GH, 1, 1)
momgru_kernel(const float* __restrict__ x,
              const float* __restrict__ W_ih,
              const float* __restrict__ W_hh,
              const float* __restrict__ b_ih,
              const float* __restrict__ b_hh,
              const float* __restrict__ Wb_x,
              const float* __restrict__ Wb_h,
              const float* __restrict__ b_beta,
              const float* __restrict__ s_ptr,
              const float* __restrict__ W_head,
              const float* __restrict__ b_head,
              float* __restrict__ out)
{
    extern __shared__ float sm[];
    float*  ws     = sm + OFF_W;
    float*  hs     = sm + OFF_H;
    float*  wbhs   = sm + OFF_WBH;
    float*  whds   = sm + OFF_WHD;
    float*  beta_s = sm + OFF_BS;
    float2* xs     = (float2*)(sm + OFF_XS);

    const unsigned sbase = smem_u32(sm);
    const unsigned mbar0 = sbase + OFF_MBAR * 4;
    const unsigned mbar1 = mbar0 + 8;

    const int tid = threadIdx.x;
    const int j   = blockIdx.x & (GH - 1);    // hidden block / cluster rank
    const int i   = blockIdx.x >> 3;          // batch block
    const int b0  = i * BB;
    const int u0  = j * UPC;

    const int u  = tid >> 3;        // 0..31  hidden unit (local)
    const int bq = (tid >> 2) & 1;  // 0..1   batch quad
    const int ks = tid & 3;         // 0..3   K-split lane
    const int bg = bq * 4 + ks;     // 0..7   this thread's gate-owned batch

    // ---- one-time preload ----------------------------------------------------
    for (int e = tid; e < NROWS * HID; e += NTH) {
        int row = e >> 8;
        int k   = e & (HID - 1);
        int g   = row >> 5;
        int uu  = row & 31;
        ws[row * RSW + k] = W_hh[(g * HID + u0 + uu) * HID + k];
    }
    for (int e = tid; e < HID; e += NTH) {
        wbhs[e] = Wb_h[e];
        whds[e] = W_head[e];
    }
    const float wbx0  = __ldg(Wb_x);
    const float wbx1  = __ldg(Wb_x + 1);
    const float bbeta = __ldg(b_beta);
    const float sv    = __ldg(s_ptr);
    const float bhead = __ldg(b_head);

    float2 wihg[3];
    float  bihg[3], bhhg[3];
    #pragma unroll
    for (int g = 0; g < 3; ++g) {
        int gr  = g * HID + u0 + u;
        wihg[g] = make_float2(__ldg(W_ih + gr * 2), __ldg(W_ih + gr * 2 + 1));
        bihg[g] = __ldg(b_ih + gr);
        bhhg[g] = __ldg(b_hh + gr);
    }

    // zero h0 (each CTA zeroes a disjoint 256-float slice of buffer 0)
    {
        float* gz = &g_h[0][0][0];
        int base  = blockIdx.x * (HID * BATCH / NCTA);   // 256 floats
        __stcg(gz + base + tid, 0.0f);
    }

    if (tid == 0) { mbar_init(mbar0, GH); mbar_init(mbar1, GH); }
    __syncthreads();
    CLUSTER_SYNC_();   // once: peers' mbarrier init + h0 zeros visible

    // per-thread momentum state for (u, bg)
    float v0 = 0.f, v1 = 0.f, v2 = 0.f;

    const float* w0p = ws + (0 * UPC + u) * RSW + ks * 4;
    const float* w1p = ws + (1 * UPC + u) * RSW + ks * 4;
    const float* w2p = ws + (2 * UPC + u) * RSW + ks * 4;
    const float* h0p = hs + (bq * 4 + 0) * RSH + ks * 4;
    const float* h1p = hs + (bq * 4 + 1) * RSH + ks * 4;
    const float* h2p = hs + (bq * 4 + 2) * RSH + ks * 4;
    const float* h3p = hs + (bq * 4 + 3) * RSH + ks * 4;

    const int bb = tid >> 3;        // beta batch (tid<64)
    const int kc = tid & 7;         // beta K-chunk lane

    unsigned ph0 = 0, ph1 = 0;

    for (int t = 0; t < SEQ; ++t) {
        // x prefetch BEFORE the wait (independent of peers' h)
        float2 xv = make_float2(0.f, 0.f);
        if (tid < 64 && kc == 0)
            xv = __ldg((const float2*)x + (b0 + bb) * SEQ + t);

        if (t > 0) {                       // wait on bar[(t-1)&1]
            if ((t - 1) & 1) { mbar_wait(mbar1, ph1); ph1 ^= 1; }
            else             { mbar_wait(mbar0, ph0); ph0 ^= 1; }
        }

        // ---- load h_t -> smem [b][k] (2 x LDG.128 per thread) --------------
        {
            const float* hsrc = &g_h[t & 1][b0][0];
            float4 hv0 = __ldcg((const float4*)hsrc + tid);
            float4 hv1 = __ldcg((const float4*)hsrc + NTH + tid);
            int e = tid;
            *(float4*)(hs + (e >> 6) * RSH + (e & 63) * 4) = hv0;
            e = tid + NTH;
            *(float4*)(hs + (e >> 6) * RSH + (e & 63) * 4) = hv1;
        }
        __syncthreads();

        // ---- beta: h . Wb_h (warps 0-1 only; 8 batches x 8 k-chunks) -------
        if (tid < 64) {
            const float* hrow = hs + bb * RSH + kc * 4;
            const float* wrow = wbhs + kc * 4;
            float2 a2 = make_float2(0.f, 0.f);
            #pragma unroll
            for (int kk = 0; kk < 8; ++kk) {
                float4 h4 = *(const float4*)(hrow + kk * 32);
                float4 w4 = *(const float4*)(wrow + kk * 32);
                a2 = ffma2(make_float2(w4.x, w4.y), make_float2(h4.x, h4.y), a2);
                a2 = ffma2(make_float2(w4.z, w4.w), make_float2(h4.z, h4.w), a2);
            }
            float a = a2.x + a2.y;
            a += __shfl_xor_sync(0xffffffffu, a, 1);
            a += __shfl_xor_sync(0xffffffffu, a, 2);
            a += __shfl_xor_sync(0xffffffffu, a, 4);
            if (kc == 0) {
                float bval = sigf(xv.x * wbx0 + xv.y * wbx1 + a + bbeta);
                beta_s[bb] = bval;
                xs[bb]     = xv;
                if (j == 0) out[BATCH + (b0 + bb) * SEQ + t] = bval;
            }
        }

        // ---- gh = h @ W_hh^T : f32x2 over K, per-thread (3 gates x 4 b) ----
        float2 acc[3][4];
        #pragma unroll
        for (int g = 0; g < 3; ++g)
            #pragma unroll
            for (int bi = 0; bi < 4; ++bi) acc[g][bi] = make_float2(0.f, 0.f);

        #pragma unroll
        for (int kk = 0; kk < 16; ++kk) {
            const int o = kk * 16;
            float4 w4[3], h4[4];
            w4[0] = *(const float4*)(w0p + o);
            w4[1] = *(const float4*)(w1p + o);
            w4[2] = *(const float4*)(w2p + o);
            h4[0] = *(const float4*)(h0p + o);
            h4[1] = *(const float4*)(h1p + o);
            h4[2] = *(const float4*)(h2p + o);
            h4[3] = *(const float4*)(h3p + o);
            #pragma unroll
            for (int g = 0; g < 3; ++g)
                #pragma unroll
                for (int bi = 0; bi < 4; ++bi)
                    acc[g][bi] = ffma2(make_float2(w4[g].x, w4[g].y),
                                       make_float2(h4[bi].x, h4[bi].y), acc[g][bi]);
            #pragma unroll
            for (int g = 0; g < 3; ++g)
                #pragma unroll
                for (int bi = 0; bi < 4; ++bi)
                    acc[g][bi] = ffma2(make_float2(w4[g].z, w4[g].w),
                                       make_float2(h4[bi].z, h4[bi].w), acc[g][bi]);
        }

        // ---- K-split reduce (bfly over ks lanes -> full sum in all lanes) --
        float gsum[3][4];
        #pragma unroll
        for (int g = 0; g < 3; ++g)
            #pragma unroll
            for (int bi = 0; bi < 4; ++bi) {
                float sc = acc[g][bi].x + acc[g][bi].y;
                sc += __shfl_xor_sync(0xffffffffu, sc, 1);
                sc += __shfl_xor_sync(0xffffffffu, sc, 2);
                gsum[g][bi] = sc;
            }

        __syncthreads();   // beta_s / xs published

        // ---- v update + gates: thread owns (u, batch bg = bq*4+ks) ---------
        {
            const float  be    = beta_s[bg];
            const float2 xv2   = xs[bg];
            const float  hprev = hs[bg * RSH + u0 + u];

            float pr = xv2.x * wihg[0].x + xv2.y * wihg[0].y + bihg[0];
            float pz = xv2.x * wihg[1].x + xv2.y * wihg[1].y + bihg[1];
            float pn = xv2.x * wihg[2].x + xv2.y * wihg[2].y + bihg[2];
            v0 = be * v0 + sv * pr;
            v1 = be * v1 + sv * pz;
            v2 = be * v2 + sv * pn;

            float ghr = gsum[0][ks] + bhhg[0];
            float ghz = gsum[1][ks] + bhhg[1];
            float ghn = gsum[2][ks] + bhhg[2];

            float r  = sigf(v0 + ghr);
            float z  = sigf(v1 + ghz);
            float n  = tanh_fast(v2 + r * ghn);
            float hn = (1.0f - z) * n + z * hprev;

            __stcg(&g_h[(t + 1) & 1][b0 + bg][u0 + u], hn);
        }

        __syncthreads();   // all stcg issued before the publish threads fence
        if (tid < GH) {
            asm volatile("fence.acq_rel.cluster;" ::: "memory");
            mbar_arrive_peer((t & 1) ? mbar1 : mbar0, (unsigned)tid);
        }
    }

    mbar_wait(mbar1, ph1);   // last arrive was bar[(SEQ-1)&1] = bar1; h_T visible

    // ---- head: out[b] = h_T . W_head + b_head (rank-0 CTA per batch block) -
    if (j == 0 && tid < 64) {
        int b = tid >> 3;
        const float* hT = &g_h[0][b0 + b][0];
        float2 a2 = make_float2(0.f, 0.f);
        #pragma unroll
        for (int kk = 0; kk < 8; ++kk) {
            float4 h4 = __ldcg((const float4*)(hT + kc * 4 + kk * 32));
            float4 w4 = *(const float4*)(whds + kc * 4 + kk * 32);
            a2 = ffma2(make_float2(w4.x, w4.y), make_float2(h4.x, h4.y), a2);
            a2 = ffma2(make_float2(w4.z, w4.w), make_float2(h4.z, h4.w), a2);
        }
        float a = a2.x + a2.y;
        a += __shfl_xor_sync(0xffffffffu, a, 1);
        a += __shfl_xor_sync(0xffffffffu, a, 2);
        a += __shfl_xor_sync(0xffffffffu, a, 4);
        if (kc == 0) out[b0 + b] = a + bhead;
    }
}

extern "C" void kernel_launch(void* const* d_in, const int* in_sizes, int n_in,
                              void* d_out, int out_size) {
    const float* x      = (const float*)d_in[0];
    const float* W_ih   = (const float*)d_in[1];
    const float* W_hh   = (const float*)d_in[2];
    const float* b_ih   = (const float*)d_in[3];
    const float* b_hh   = (const float*)d_in[4];
    const float* Wb_x   = (const float*)d_in[5];
    const float* Wb_h   = (const float*)d_in[6];
    const float* b_beta = (const float*)d_in[7];
    const float* s      = (const float*)d_in[8];
    const float* W_head = (const float*)d_in[9];
    const float* b_head = (const float*)d_in[10];

    cudaFuncSetAttribute(momgru_kernel,
                         cudaFuncAttributeMaxDynamicSharedMemorySize,
                         SMEM_BYTES);

    momgru_kernel<<<NCTA, NTH, SMEM_BYTES>>>(
        x, W_ih, W_hh, b_ih, b_hh, Wb_x, Wb_h, b_beta, s, W_head, b_head,
        (float*)d_out);
}

// round 7
// speedup vs baseline: 3.1004x; 2.6018x over previous
#include <cuda_runtime.h>

// ---------------------------------------------------------------------------
// MomGRU persistent recurrence, round 7.
// Grid 128 CTAs = 32 batch-blocks x 4 hidden-blocks; cluster(4) per batch
// block. 256 threads. Thread tile: 6 gate-rows (2u x 3g) x 4 batches,
// K split 8-way; reduce-scatter butterfly delivers each thread its own
// (u, b) sums. h exchanged via stcg/ldcg in L2 under the aligned cluster
// barrier (R2-proven). Weights SMEM-stationary (208 KB).
// ---------------------------------------------------------------------------

namespace {
constexpr int BATCH = 128;
constexpr int SEQ   = 1024;
constexpr int HID   = 256;
constexpr int GB    = 32;              // batch blocks
constexpr int GH    = 4;               // hidden blocks (= cluster size)
constexpr int NCTA  = GB * GH;         // 128
constexpr int BB    = BATCH / GB;      // 4 batches per CTA
constexpr int UPC   = HID / GH;        // 64 hidden units per CTA
constexpr int NROWS = 3 * UPC;         // 192 W_hh rows per CTA
constexpr int NTH   = 256;
constexpr int RSW   = HID + 16;        // 272 weight row stride (floats)
constexpr int RSH   = HID + 4;         // 260 h row stride (floats)

// smem layout (floats)
constexpr int OFF_W   = 0;                       // NROWS * RSW = 52224
constexpr int OFF_H   = OFF_W + NROWS * RSW;     // BB * RSH = 1040
constexpr int OFF_WBH = OFF_H + BB * RSH;        // HID
constexpr int OFF_WHD = OFF_WBH + HID;           // HID
constexpr int OFF_BS  = OFF_WHD + HID;           // BB
constexpr int OFF_XS  = OFF_BS + BB;             // BB float2
constexpr int SMEM_FLOATS = OFF_XS + BB * 2;
constexpr int SMEM_BYTES  = SMEM_FLOATS * 4;     // ~215.2 KB
}

// persistent h ping-pong, layout [buf][batch][hid]
__device__ float g_h[2][BATCH][HID];

// ---- packed fp32x2 helpers -------------------------------------------------
__device__ __forceinline__ unsigned long long pk2(float2 v) {
    unsigned long long r;
    asm("mov.b64 %0, {%1,%2};" : "=l"(r) : "f"(v.x), "f"(v.y));
    return r;
}
__device__ __forceinline__ float2 upk2(unsigned long long v) {
    float2 r;
    asm("mov.b64 {%0,%1}, %2;" : "=f"(r.x), "=f"(r.y) : "l"(v));
    return r;
}
__device__ __forceinline__ float2 ffma2(float2 a, float2 b, float2 c) {
    unsigned long long d;
    asm("fma.rn.f32x2 %0, %1, %2, %3;"
        : "=l"(d) : "l"(pk2(a)), "l"(pk2(b)), "l"(pk2(c)));
    return upk2(d);
}

__device__ __forceinline__ float sigf(float x) {
    return __fdividef(1.0f, 1.0f + __expf(-x));
}
__device__ __forceinline__ float tanh_fast(float x) {
    float ax = fabsf(x);
    float e  = __expf(-2.0f * ax);
    return copysignf(__fdividef(1.0f - e, 1.0f + e), x);
}

// Reduce-scatter over 8 ks lanes: v[8] = per-lane partial sums for slots 0..7;
// returns the full sum of slot 'ks' on lane with K-split index ks.
__device__ __forceinline__ float reduce_scatter8(const float v[8], int ks) {
    float w[4];
    #pragma unroll
    for (int i = 0; i < 4; ++i) {
        float mine  = (ks & 4) ? v[i + 4] : v[i];
        float their = (ks & 4) ? v[i]     : v[i + 4];
        w[i] = mine + __shfl_xor_sync(0xffffffffu, their, 4);
    }
    float y[2];
    #pragma unroll
    for (int i = 0; i < 2; ++i) {
        float mine  = (ks & 2) ? w[i + 2] : w[i];
        float their = (ks & 2) ? w[i]     : w[i + 2];
        y[i] = mine + __shfl_xor_sync(0xffffffffu, their, 2);
    }
    float mine  = (ks & 1) ? y[1] : y[0];
    float their = (ks & 1) ? y[0] : y[1];
    return mine + __shfl_xor_sync(0xffffffffu, their, 1);
}

#define CLUSTER_ARRIVE() asm volatile("barrier.cluster.arrive.aligned;" ::: "memory")
#define CLUSTER_WAIT()   asm volatile("barrier.cluster.wait.aligned;"   ::: "memory")

extern "C" __global__ void __launch_bounds__(NTH, 1) __cluster_dims__(GH, 1, 1)
momgru_kernel(const float* __restrict__ x,
              const float* __restrict__ W_ih,
              const float* __restrict__ W_hh,
              const float* __restrict__ b_ih,
              const float* __restrict__ b_hh,
              const float* __restrict__ Wb_x,
              const float* __restrict__ Wb_h,
              const float* __restrict__ b_beta,
              const float* __restrict__ s_ptr,
              const float* __restrict__ W_head,
              const float* __restrict__ b_head,
              float* __restrict__ out)
{
    extern __shared__ float sm[];
    float*  ws     = sm + OFF_W;
    float*  hs     = sm + OFF_H;
    float*  wbhs   = sm + OFF_WBH;
    float*  whds   = sm + OFF_WHD;
    float*  beta_s = sm + OFF_BS;
    float2* xs     = (float2*)(sm + OFF_XS);

    const int tid = threadIdx.x;
    const int j   = blockIdx.x & (GH - 1);    // hidden block / cluster rank
    const int i   = blockIdx.x >> 2;          // batch block
    const int b0  = i * BB;
    const int u0  = j * UPC;

    const int up = tid >> 3;        // 0..31  u-pair index (u = 2*up + uu2)
    const int ks = tid & 7;         // 0..7   K-split lane
    const int uo = up * 2 + (ks >> 2);   // owned local u (0..63)
    const int bo = ks & 3;               // owned local batch (0..3)

    // ---- one-time preload ----------------------------------------------------
    for (int e = tid; e < NROWS * HID; e += NTH) {
        int row = e >> 8;           // 0..191
        int k   = e & (HID - 1);
        int g   = row >> 6;         // gate
        int uu  = row & 63;
        ws[row * RSW + k] = W_hh[(g * HID + u0 + uu) * HID + k];
    }
    for (int e = tid; e < HID; e += NTH) {
        wbhs[e] = Wb_h[e];
        whds[e] = W_head[e];
    }
    const float wbx0  = __ldg(Wb_x);
    const float wbx1  = __ldg(Wb_x + 1);
    const float bbeta = __ldg(b_beta);
    const float sv    = __ldg(s_ptr);
    const float bhead = __ldg(b_head);

    float2 wihg[3];
    float  bihg[3], bhhg[3];
    #pragma unroll
    for (int g = 0; g < 3; ++g) {
        int gr  = g * HID + u0 + uo;
        wihg[g] = make_float2(__ldg(W_ih + gr * 2), __ldg(W_ih + gr * 2 + 1));
        bihg[g] = __ldg(b_ih + gr);
        bhhg[g] = __ldg(b_hh + gr);
    }

    // zero h0 (each CTA zeroes a disjoint 256-float slice of buffer 0)
    {
        float* gz = &g_h[0][0][0];
        __stcg(gz + blockIdx.x * NTH + tid, 0.0f);
    }
    CLUSTER_ARRIVE();   // release: h0 zeros visible at first wait

    // per-thread momentum state for (uo, bo)
    float v0 = 0.f, v1 = 0.f, v2 = 0.f;

    // weight row pointers: rows g*64 + 2*up + uu2
    const float* wp[3][2];
    #pragma unroll
    for (int g = 0; g < 3; ++g)
        #pragma unroll
        for (int q = 0; q < 2; ++q)
            wp[g][q] = ws + (g * UPC + up * 2 + q) * RSW + ks * 4;

    const float* hp[4];
    #pragma unroll
    for (int b = 0; b < 4; ++b)
        hp[b] = hs + b * RSH + ks * 4;

    const int bb = tid >> 4;        // beta batch (tid<64): 0..3
    const int kc = tid & 15;        // beta K-chunk lane

    for (int t = 0; t < SEQ; ++t) {
        // x prefetch BEFORE the wait (independent of peers' h)
        float2 xv = make_float2(0.f, 0.f);
        if (tid < 64 && kc == 0)
            xv = __ldg((const float2*)x + (b0 + bb) * SEQ + t);

        CLUSTER_WAIT();   // acquire: peers' h_t stores visible in L2

        // ---- load h_t -> smem staging (1 LDG.128 per thread, contiguous) ----
        {
            const float* hsrc = &g_h[t & 1][b0][0];
            float4 hv = __ldcg((const float4*)hsrc + tid);
            int b = tid >> 6;
            int q = tid & 63;
            *(float4*)(hs + b * RSH + q * 4) = hv;
        }
        __syncthreads();

        // ---- beta: h . Wb_h (warps 0-1; 4 batches x 16 k-chunks) -------------
        if (tid < 64) {
            const float* hrow = hs + bb * RSH + kc * 4;
            const float* wrow = wbhs + kc * 4;
            float2 a2 = make_float2(0.f, 0.f);
            #pragma unroll
            for (int kk = 0; kk < 4; ++kk) {
                float4 h4 = *(const float4*)(hrow + kk * 64);
                float4 w4 = *(const float4*)(wrow + kk * 64);
                a2 = ffma2(make_float2(w4.x, w4.y), make_float2(h4.x, h4.y), a2);
                a2 = ffma2(make_float2(w4.z, w4.w), make_float2(h4.z, h4.w), a2);
            }
            float a = a2.x + a2.y;
            a += __shfl_xor_sync(0xffffffffu, a, 1);
            a += __shfl_xor_sync(0xffffffffu, a, 2);
            a += __shfl_xor_sync(0xffffffffu, a, 4);
            a += __shfl_xor_sync(0xffffffffu, a, 8);
            if (kc == 0) {
                float bval = sigf(xv.x * wbx0 + xv.y * wbx1 + a + bbeta);
                beta_s[bb] = bval;
                xs[bb]     = xv;
                if (j == 0) out[BATCH + (b0 + bb) * SEQ + t] = bval;
            }
        }

        // ---- gh = h @ W_hh^T : 6 rows x 4 batches per thread, K/8 -----------
        float2 acc[3][2][4];
        #pragma unroll
        for (int g = 0; g < 3; ++g)
            #pragma unroll
            for (int q = 0; q < 2; ++q)
                #pragma unroll
                for (int b = 0; b < 4; ++b) acc[g][q][b] = make_float2(0.f, 0.f);

        #pragma unroll
        for (int kk = 0; kk < 8; ++kk) {
            const int o = kk * 32;
            float4 h4[4];
            #pragma unroll
            for (int b = 0; b < 4; ++b) h4[b] = *(const float4*)(hp[b] + o);
            #pragma unroll
            for (int g = 0; g < 3; ++g)
                #pragma unroll
                for (int q = 0; q < 2; ++q) {
                    float4 w4 = *(const float4*)(wp[g][q] + o);
                    float2 wa = make_float2(w4.x, w4.y);
                    float2 wb = make_float2(w4.z, w4.w);
                    #pragma unroll
                    for (int b = 0; b < 4; ++b) {
                        acc[g][q][b] = ffma2(wa, make_float2(h4[b].x, h4[b].y), acc[g][q][b]);
                        acc[g][q][b] = ffma2(wb, make_float2(h4[b].z, h4[b].w), acc[g][q][b]);
                    }
                }
        }

        // ---- reduce-scatter over ks lanes: thread keeps its own (uo,bo) ------
        float gh[3];
        #pragma unroll
        for (int g = 0; g < 3; ++g) {
            float v[8];
            #pragma unroll
            for (int q = 0; q < 2; ++q)
                #pragma unroll
                for (int b = 0; b < 4; ++b)
                    v[q * 4 + b] = acc[g][q][b].x + acc[g][q][b].y;
            gh[g] = reduce_scatter8(v, ks) + bhhg[g];
        }

        __syncthreads();   // beta_s / xs published

        // ---- v update + gates: thread owns (uo, bo) --------------------------
        {
            const float  be    = beta_s[bo];
            const float2 xv2   = xs[bo];
            const float  hprev = hs[bo * RSH + u0 + uo];

            float pr = xv2.x * wihg[0].x + xv2.y * wihg[0].y + bihg[0];
            float pz = xv2.x * wihg[1].x + xv2.y * wihg[1].y + bihg[1];
            float pn = xv2.x * wihg[2].x + xv2.y * wihg[2].y + bihg[2];
            v0 = be * v0 + sv * pr;
            v1 = be * v1 + sv * pz;
            v2 = be * v2 + sv * pn;

            float r  = sigf(v0 + gh[0]);
            float z  = sigf(v1 + gh[1]);
            float n  = tanh_fast(v2 + r * gh[2]);
            float hn = (1.0f - z) * n + z * hprev;

            __stcg(&g_h[(t + 1) & 1][b0 + bo][u0 + uo], hn);
        }

        CLUSTER_ARRIVE();  // release h_{t+1} stores
    }

    CLUSTER_WAIT();        // final h_T (buffer 0) visible

    // ---- head: out[b] = h_T . W_head + b_head (rank-0 CTA per batch block) ---
    if (j == 0 && tid < 64) {
        int b = tid >> 4;
        const float* hT = &g_h[0][b0 + b][0];
        float2 a2 = make_float2(0.f, 0.f);
        #pragma unroll
        for (int kk = 0; kk < 4; ++kk) {
            float4 h4 = __ldcg((const float4*)(hT + kc * 4 + kk * 64));
            float4 w4 = *(const float4*)(whds + kc * 4 + kk * 64);
            a2 = ffma2(make_float2(w4.x, w4.y), make_float2(h4.x, h4.y), a2);
            a2 = ffma2(make_float2(w4.z, w4.w), make_float2(h4.z, h4.w), a2);
        }
        float a = a2.x + a2.y;
        a += __shfl_xor_sync(0xffffffffu, a, 1);
        a += __shfl_xor_sync(0xffffffffu, a, 2);
        a += __shfl_xor_sync(0xffffffffu, a, 4);
        a += __shfl_xor_sync(0xffffffffu, a, 8);
        if (kc == 0) out[b0 + b] = a + bhead;
    }
}

extern "C" void kernel_launch(void* const* d_in, const int* in_sizes, int n_in,
                              void* d_out, int out_size) {
    const float* x      = (const float*)d_in[0];
    const float* W_ih   = (const float*)d_in[1];
    const float* W_hh   = (const float*)d_in[2];
    const float* b_ih   = (const float*)d_in[3];
    const float* b_hh   = (const float*)d_in[4];
    const float* Wb_x   = (const float*)d_in[5];
    const float* Wb_h   = (const float*)d_in[6];
    const float* b_beta = (const float*)d_in[7];
    const float* s      = (const float*)d_in[8];
    const float* W_head = (const float*)d_in[9];
    const float* b_head = (const float*)d_in[10];

    cudaFuncSetAttribute(momgru_kernel,
                         cudaFuncAttributeMaxDynamicSharedMemorySize,
                         SMEM_BYTES);

    momgru_kernel<<<NCTA, NTH, SMEM_BYTES>>>(
        x, W_ih, W_hh, b_ih, b_hh, Wb_x, Wb_h, b_beta, s, W_head, b_head,
        (float*)d_out);
}